// round 8
// baseline (speedup 1.0000x reference)
#include <cuda_runtime.h>
#include <cuda_bf16.h>
#include <math.h>

// ---- Physical constants, folded at compile time ----
namespace mk {
constexpr double R_      = 3.0 * 0.0254;
constexpr double LSUM    = 0.129907 + 0.095724;
constexpr double G_      = 13.7;
constexpr double MASS_   = 12.0;
constexpr double MOI_    = MASS_ * (12.0 * 0.0254) * (12.0 * 0.0254) / 6.0;

constexpr float INV_R  = (float)(1.0 / R_);
constexpr float L_R    = (float)(LSUM / R_);
constexpr float T_DUTY = (float)(0.193 * G_);
constexpr float T_VEL  = (float)(G_ * 0.000304 * G_);
constexpr float T_FRIC = (float)(0.00317 * G_);
constexpr float K_XY   = (float)(1.0 / (4.0 * R_ * MASS_));
constexpr float K_W    = (float)(1.0 / (4.0 * LSUM * R_ * MOI_));
constexpr float EPS    = 0.01f;
}

// MUFU-path math: inputs are N(0,1) (|theta| <~ 5.5) where sin/cos.approx are
// ~1e-6 accurate; measured rel_err 9e-8 against the 1e-3 tolerance.
__device__ __forceinline__ void fast_sincos(float x, float& s, float& c) {
    asm("sin.approx.f32 %0, %1;" : "=f"(s) : "f"(x));
    asm("cos.approx.f32 %0, %1;" : "=f"(c) : "f"(x));
}
__device__ __forceinline__ float fast_rsqrt(float x) {
    float r;
    asm("rsqrt.approx.f32 %0, %1;" : "=f"(r) : "f"(x));
    return r;
}

__device__ __forceinline__ void mecanum_row(
    float theta, float vx, float vy, float wz,
    float u0, float u1, float u2,
    float& ax, float& ay, float& aw)
{
    float st, ct;
    fast_sincos(theta, st, ct);

    // local velocity (rotation by -theta)
    float lvx =  ct * vx + st * vy;
    float lvy = -st * vx + ct * vy;

    // wheel velocities
    float p  = mk::INV_R * (lvx + lvy);
    float m  = mk::INV_R * (lvx - lvy);
    float lz = mk::L_R * wz;
    float w0 = m - lz;
    float w1 = p + lz;
    float w2 = p - lz;
    float w3 = m + lz;

    // motor duty
    float m0 = u0 - u1 - u2;
    float m1 = u0 + u1 + u2;
    float m2 = u0 + u1 - u2;
    float m3 = u0 - u1 + u2;

    // wheel torque
    float t0 = mk::T_DUTY * m0 - mk::T_VEL * w0 - mk::T_FRIC * (w0 * fast_rsqrt(w0 * w0 + mk::EPS));
    float t1 = mk::T_DUTY * m1 - mk::T_VEL * w1 - mk::T_FRIC * (w1 * fast_rsqrt(w1 * w1 + mk::EPS));
    float t2 = mk::T_DUTY * m2 - mk::T_VEL * w2 - mk::T_FRIC * (w2 * fast_rsqrt(w2 * w2 + mk::EPS));
    float t3 = mk::T_DUTY * m3 - mk::T_VEL * w3 - mk::T_FRIC * (w3 * fast_rsqrt(w3 * w3 + mk::EPS));

    // local acceleration (analytic pinv of the 4x3 wheel matrix)
    float la0 = mk::K_XY * ( t0 + t1 + t2 + t3);
    float la1 = mk::K_XY * (-t0 + t1 + t2 - t3);
    float la2 = mk::K_W  * (-t0 + t1 - t2 + t3);

    // rotate back by +theta (A^T)
    ax = ct * la0 - st * la1;
    ay = st * la0 + ct * la1;
    aw = la2;
}

// loads for row i: 2x float2 (state, 8-aligned) + 3 scalars (ctrl).
// x,y fields of state are never loaded.
__device__ __forceinline__ void load_row(
    const float* __restrict__ state, const float* __restrict__ ctrl,
    size_t i, float2& tv, float2& vw, float& u0, float& u1, float& u2)
{
    const float2* s2 = reinterpret_cast<const float2*>(state + 6 * i + 2);
    tv = s2[0];                 // theta, vx
    vw = s2[1];                 // vy, wz
    const float* u = ctrl + 3 * i;
    u0 = u[0]; u1 = u[1]; u2 = u[2];
}

__device__ __forceinline__ void compute_store_row(
    float* __restrict__ out, size_t i,
    float2 tv, float2 vw, float u0, float u1, float u2)
{
    float ax, ay, aw;
    mecanum_row(tv.x, tv.y, vw.x, vw.y, u0, u1, u2, ax, ay, aw);
    // streaming stores: output is write-only; evict-first keeps the inputs
    // L2-resident across graph replays.
    float2* o2 = reinterpret_cast<float2*>(out + 6 * i);
    __stcs(o2 + 0, make_float2(tv.y, vw.x));   // vx, vy
    __stcs(o2 + 1, make_float2(vw.y, ax));     // wz, ax
    __stcs(o2 + 2, make_float2(ay, aw));       // ay, aw
}

// ---- Grid-stride persistent kernel with 2-stage software pipeline ----
// Keeps the proven 24B/12B lane-stride access pattern (same wavefront count
// per row as the R4/R7 winner) but:
//  * grid sized to exactly fill the chip -> no partial-wave tail
//  * loads for iteration i+1 are issued before computing iteration i,
//    so each warp always has ~5 loads in flight during compute.
__global__ void __launch_bounds__(256, 6)
mecanum_gs_kernel(const float* __restrict__ state,
                  const float* __restrict__ ctrl,
                  float* __restrict__ out,
                  int B)
{
    const int T = gridDim.x * blockDim.x;
    int i = blockIdx.x * blockDim.x + threadIdx.x;
    if (i >= B) return;

    float2 tv, vw; float u0, u1, u2;
    load_row(state, ctrl, (size_t)i, tv, vw, u0, u1, u2);

    for (;;) {
        int inext = i + T;
        bool has = inext < B;
        float2 tv2, vw2; float v0, v1, v2;
        if (has) load_row(state, ctrl, (size_t)inext, tv2, vw2, v0, v1, v2);

        compute_store_row(out, (size_t)i, tv, vw, u0, u1, u2);

        if (!has) break;
        i = inext;
        tv = tv2; vw = vw2; u0 = v0; u1 = v1; u2 = v2;
    }
}

extern "C" void kernel_launch(void* const* d_in, const int* in_sizes, int n_in,
                              void* d_out, int out_size)
{
    // metadata order: t (1), state (B*6), control_duty (B*3)
    const float* state = (const float*)d_in[1];
    const float* ctrl  = (const float*)d_in[2];
    float* out = (float*)d_out;
    int B = in_sizes[1] / 6;

    int nsm = 148;
    cudaDeviceGetAttribute(&nsm, cudaDevAttrMultiProcessorCount, 0);

    const int threads = 256;
    int blocks = nsm * 6;                      // match __launch_bounds__ occupancy
    int maxb = (B + threads - 1) / threads;    // never launch idle blocks
    if (blocks > maxb) blocks = maxb;
    if (blocks < 1) blocks = 1;

    mecanum_gs_kernel<<<blocks, threads>>>(state, ctrl, out, B);
}

// round 9
// speedup vs baseline: 1.1200x; 1.1200x over previous
#include <cuda_runtime.h>
#include <cuda_bf16.h>
#include <math.h>

// ---- Physical constants, folded at compile time ----
namespace mk {
constexpr double R_      = 3.0 * 0.0254;
constexpr double LSUM    = 0.129907 + 0.095724;
constexpr double G_      = 13.7;
constexpr double MASS_   = 12.0;
constexpr double MOI_    = MASS_ * (12.0 * 0.0254) * (12.0 * 0.0254) / 6.0;

constexpr float INV_R  = (float)(1.0 / R_);
constexpr float L_R    = (float)(LSUM / R_);
constexpr float T_DUTY = (float)(0.193 * G_);
constexpr float T_VEL  = (float)(G_ * 0.000304 * G_);
constexpr float T_FRIC = (float)(0.00317 * G_);
constexpr float K_XY   = (float)(1.0 / (4.0 * R_ * MASS_));
constexpr float K_W    = (float)(1.0 / (4.0 * LSUM * R_ * MOI_));
constexpr float EPS    = 0.01f;
}

// MUFU-path math: inputs are N(0,1) (|theta| <~ 5.5) where sin/cos.approx are
// ~1e-6 accurate; measured rel_err 9e-8 against the 1e-3 tolerance.
__device__ __forceinline__ void fast_sincos(float x, float& s, float& c) {
    asm("sin.approx.f32 %0, %1;" : "=f"(s) : "f"(x));
    asm("cos.approx.f32 %0, %1;" : "=f"(c) : "f"(x));
}
__device__ __forceinline__ float fast_rsqrt(float x) {
    float r;
    asm("rsqrt.approx.f32 %0, %1;" : "=f"(r) : "f"(x));
    return r;
}

__device__ __forceinline__ void mecanum_row(
    float theta, float vx, float vy, float wz,
    float u0, float u1, float u2,
    float& ax, float& ay, float& aw)
{
    float st, ct;
    fast_sincos(theta, st, ct);

    // local velocity (rotation by -theta)
    float lvx =  ct * vx + st * vy;
    float lvy = -st * vx + ct * vy;

    // wheel velocities
    float p  = mk::INV_R * (lvx + lvy);
    float m  = mk::INV_R * (lvx - lvy);
    float lz = mk::L_R * wz;
    float w0 = m - lz;
    float w1 = p + lz;
    float w2 = p - lz;
    float w3 = m + lz;

    // motor duty
    float m0 = u0 - u1 - u2;
    float m1 = u0 + u1 + u2;
    float m2 = u0 + u1 - u2;
    float m3 = u0 - u1 + u2;

    // wheel torque
    float t0 = mk::T_DUTY * m0 - mk::T_VEL * w0 - mk::T_FRIC * (w0 * fast_rsqrt(w0 * w0 + mk::EPS));
    float t1 = mk::T_DUTY * m1 - mk::T_VEL * w1 - mk::T_FRIC * (w1 * fast_rsqrt(w1 * w1 + mk::EPS));
    float t2 = mk::T_DUTY * m2 - mk::T_VEL * w2 - mk::T_FRIC * (w2 * fast_rsqrt(w2 * w2 + mk::EPS));
    float t3 = mk::T_DUTY * m3 - mk::T_VEL * w3 - mk::T_FRIC * (w3 * fast_rsqrt(w3 * w3 + mk::EPS));

    // local acceleration (analytic pinv of the 4x3 wheel matrix)
    float la0 = mk::K_XY * ( t0 + t1 + t2 + t3);
    float la1 = mk::K_XY * (-t0 + t1 + t2 - t3);
    float la2 = mk::K_W  * (-t0 + t1 - t2 + t3);

    // rotate back by +theta (A^T)
    ax = ct * la0 - st * la1;
    ay = st * la0 + ct * la1;
    aw = la2;
}

// ---- R7 body, grid-stride shape ----
// Body is identical to the 16.45us winner: per row, 2x float2 state loads
// (8-aligned, x/y never loaded), 3 scalar ctrl loads, 3x float2 __stcs
// streaming stores (write-only output -> evict-first keeps the 72MB of
// inputs L2-resident across graph replays).
// The ONLY change vs R7: a bare grid-stride loop (no prefetch, no double
// buffering, unroll 1) so the chip runs one persistent wave instead of 6.6
// short waves. Loop-carried state = the index. Target: regs <= 32 so the
// 8-CTAs/SM (64 warps) occupancy of R7 is preserved.
__global__ void __launch_bounds__(256, 8)
mecanum_gs_kernel(const float* __restrict__ state,
                  const float* __restrict__ ctrl,
                  float* __restrict__ out,
                  int B)
{
    const int T = gridDim.x * blockDim.x;
#pragma unroll 1
    for (int i = blockIdx.x * blockDim.x + threadIdx.x; i < B; i += T) {
        const float2* s2 = reinterpret_cast<const float2*>(state + 6 * (size_t)i + 2);
        float2 tv = s2[0];          // theta, vx
        float2 vw = s2[1];          // vy, wz

        const float* u = ctrl + 3 * (size_t)i;
        float u0 = u[0], u1 = u[1], u2 = u[2];

        float ax, ay, aw;
        mecanum_row(tv.x, tv.y, vw.x, vw.y, u0, u1, u2, ax, ay, aw);

        float2* o2 = reinterpret_cast<float2*>(out + 6 * (size_t)i);
        __stcs(o2 + 0, make_float2(tv.y, vw.x));   // vx, vy
        __stcs(o2 + 1, make_float2(vw.y, ax));     // wz, ax
        __stcs(o2 + 2, make_float2(ay, aw));       // ay, aw
    }
}

extern "C" void kernel_launch(void* const* d_in, const int* in_sizes, int n_in,
                              void* d_out, int out_size)
{
    // metadata order: t (1), state (B*6), control_duty (B*3)
    const float* state = (const float*)d_in[1];
    const float* ctrl  = (const float*)d_in[2];
    float* out = (float*)d_out;
    int B = in_sizes[1] / 6;

    int nsm = 148;
    cudaDeviceGetAttribute(&nsm, cudaDevAttrMultiProcessorCount, 0);

    const int threads = 256;
    int blocks = nsm * 8;                      // one full-occupancy persistent wave
    int maxb = (B + threads - 1) / threads;    // never launch idle blocks
    if (blocks > maxb) blocks = maxb;
    if (blocks < 1) blocks = 1;

    mecanum_gs_kernel<<<blocks, threads>>>(state, ctrl, out, B);
}

// round 10
// speedup vs baseline: 1.2491x; 1.1152x over previous
#include <cuda_runtime.h>
#include <cuda_bf16.h>
#include <math.h>

// ---- Physical constants, folded at compile time ----
namespace mk {
constexpr double R_      = 3.0 * 0.0254;
constexpr double LSUM    = 0.129907 + 0.095724;
constexpr double G_      = 13.7;
constexpr double MASS_   = 12.0;
constexpr double MOI_    = MASS_ * (12.0 * 0.0254) * (12.0 * 0.0254) / 6.0;

constexpr double T_DUTY = 0.193 * G_;          // duty -> torque
constexpr double T_VEL  = G_ * 0.000304 * G_;  // wheel vel -> torque
constexpr double T_FRIC = 0.00317 * G_;        // softsign -> torque
constexpr double K_XYd  = 1.0 / (4.0 * R_ * MASS_);
constexpr double K_Wd   = 1.0 / (4.0 * LSUM * R_ * MOI_);

// wheel-velocity build
constexpr float INV_R = (float)(1.0 / R_);
constexpr float L_R   = (float)(LSUM / R_);
constexpr float EPS   = 0.01f;

// Collapsed-chain constants. Using the analytic pinv sign patterns,
//   Sigma(+-m_k) = 4*u{0,1,2}  and  Sigma(+-w_k) = {4 lvx/R, 4 lvy/R, 4 L w/R},
// so the duty and damping paths reduce to single FMAs; only the four
// softsign terms need per-wheel work.
constexpr float A_XY = (float)(4.0 * K_XYd * T_DUTY);          // * u0,u1
constexpr float B_XY = (float)(4.0 * K_XYd * T_VEL / R_);      // * lvx,lvy
constexpr float C_XY = (float)(K_XYd * T_FRIC);                // * ss sums
constexpr float A_W  = (float)(4.0 * K_Wd * T_DUTY);           // * u2
constexpr float B_W  = (float)(4.0 * K_Wd * T_VEL * LSUM / R_);// * wz
constexpr float C_W  = (float)(K_Wd * T_FRIC);                 // * ss sum
}

// MUFU-path math: inputs are N(0,1) (|theta| <~ 5.5) where sin/cos.approx are
// ~1e-6 accurate; measured rel_err 9e-8 against the 1e-3 tolerance.
__device__ __forceinline__ void fast_sincos(float x, float& s, float& c) {
    asm("sin.approx.f32 %0, %1;" : "=f"(s) : "f"(x));
    asm("cos.approx.f32 %0, %1;" : "=f"(c) : "f"(x));
}
__device__ __forceinline__ float fast_rsqrt(float x) {
    float r;
    asm("rsqrt.approx.f32 %0, %1;" : "=f"(r) : "f"(x));
    return r;
}

__device__ __forceinline__ void mecanum_row(
    float theta, float vx, float vy, float wz,
    float u0, float u1, float u2,
    float& ax, float& ay, float& aw)
{
    float st, ct;
    fast_sincos(theta, st, ct);

    // local velocity (rotation by -theta)
    float lvx =  ct * vx + st * vy;
    float lvy = -st * vx + ct * vy;

    // wheel velocities (needed only for the softsign friction terms)
    float p  = mk::INV_R * (lvx + lvy);
    float m  = mk::INV_R * (lvx - lvy);
    float lz = mk::L_R * wz;
    float w0 = m - lz;
    float w1 = p + lz;
    float w2 = p - lz;
    float w3 = m + lz;

    float ss0 = w0 * fast_rsqrt(w0 * w0 + mk::EPS);
    float ss1 = w1 * fast_rsqrt(w1 * w1 + mk::EPS);
    float ss2 = w2 * fast_rsqrt(w2 * w2 + mk::EPS);
    float ss3 = w3 * fast_rsqrt(w3 * w3 + mk::EPS);

    // sign-pattern sums:  S0 = ++++ , S1 = -++- , S2 = -+-+
    float a = ss0 + ss3, b = ss1 + ss2;
    float S0 = a + b;
    float S1 = b - a;
    float S2 = (ss1 - ss2) + (ss3 - ss0);

    // collapsed local acceleration
    float la0 = mk::A_XY * u0 - mk::B_XY * lvx - mk::C_XY * S0;
    float la1 = mk::A_XY * u1 - mk::B_XY * lvy - mk::C_XY * S1;
    float la2 = mk::A_W  * u2 - mk::B_W  * wz  - mk::C_W  * S2;

    // rotate back by +theta (A^T)
    ax = ct * la0 - st * la1;
    ay = st * la0 + ct * la1;
    aw = la2;
}

// ---- One row per thread (R7 winner shape), collapsed math, 128-thr blocks ----
// Per row: 2x float2 state loads (8-aligned; x,y never loaded), 3 scalar ctrl
// loads, 3x float2 __stcs streaming stores (write-only output -> evict-first
// keeps the 72MB of inputs L2-resident across graph replays).
__global__ void __launch_bounds__(128, 16)
mecanum_row_kernel(const float* __restrict__ state,
                   const float* __restrict__ ctrl,
                   float* __restrict__ out,
                   int B)
{
    int i = blockIdx.x * blockDim.x + threadIdx.x;
    if (i >= B) return;

    const float2* s2 = reinterpret_cast<const float2*>(state + 6 * (size_t)i + 2);
    float2 tv = s2[0];          // theta, vx
    float2 vw = s2[1];          // vy, wz

    const float* u = ctrl + 3 * (size_t)i;
    float u0 = u[0], u1 = u[1], u2 = u[2];

    float ax, ay, aw;
    mecanum_row(tv.x, tv.y, vw.x, vw.y, u0, u1, u2, ax, ay, aw);

    float2* o2 = reinterpret_cast<float2*>(out + 6 * (size_t)i);
    __stcs(o2 + 0, make_float2(tv.y, vw.x));   // vx, vy
    __stcs(o2 + 1, make_float2(vw.y, ax));     // wz, ax
    __stcs(o2 + 2, make_float2(ay, aw));       // ay, aw
}

extern "C" void kernel_launch(void* const* d_in, const int* in_sizes, int n_in,
                              void* d_out, int out_size)
{
    // metadata order: t (1), state (B*6), control_duty (B*3)
    const float* state = (const float*)d_in[1];
    const float* ctrl  = (const float*)d_in[2];
    float* out = (float*)d_out;
    int B = in_sizes[1] / 6;

    int threads = 128;
    int blocks = (B + threads - 1) / threads;
    mecanum_row_kernel<<<blocks, threads>>>(state, ctrl, out, B);
}

// round 11
// speedup vs baseline: 1.2751x; 1.0209x over previous
#include <cuda_runtime.h>
#include <cuda_bf16.h>
#include <math.h>

// ---- Physical constants, folded at compile time ----
namespace mk {
constexpr double R_      = 3.0 * 0.0254;
constexpr double LSUM    = 0.129907 + 0.095724;
constexpr double G_      = 13.7;
constexpr double MASS_   = 12.0;
constexpr double MOI_    = MASS_ * (12.0 * 0.0254) * (12.0 * 0.0254) / 6.0;

constexpr double T_DUTY = 0.193 * G_;          // duty -> torque
constexpr double T_VEL  = G_ * 0.000304 * G_;  // wheel vel -> torque
constexpr double T_FRIC = 0.00317 * G_;        // softsign -> torque
constexpr double K_XYd  = 1.0 / (4.0 * R_ * MASS_);
constexpr double K_Wd   = 1.0 / (4.0 * LSUM * R_ * MOI_);

constexpr float INV_R = (float)(1.0 / R_);
constexpr float L_R   = (float)(LSUM / R_);
constexpr float EPS   = 0.01f;

// Collapsed-chain constants (analytic pinv sign patterns make the duty and
// damping paths telescope to single FMAs; only softsign needs per-wheel work)
constexpr float A_XY = (float)(4.0 * K_XYd * T_DUTY);
constexpr float B_XY = (float)(4.0 * K_XYd * T_VEL / R_);
constexpr float C_XY = (float)(K_XYd * T_FRIC);
constexpr float A_W  = (float)(4.0 * K_Wd * T_DUTY);
constexpr float B_W  = (float)(4.0 * K_Wd * T_VEL * LSUM / R_);
constexpr float C_W  = (float)(K_Wd * T_FRIC);
}

// MUFU-path math: inputs are N(0,1) (|theta| <~ 5.5) where sin/cos.approx are
// ~1e-6 accurate; measured rel_err 8e-8 against the 1e-3 tolerance.
__device__ __forceinline__ void fast_sincos(float x, float& s, float& c) {
    asm("sin.approx.f32 %0, %1;" : "=f"(s) : "f"(x));
    asm("cos.approx.f32 %0, %1;" : "=f"(c) : "f"(x));
}
__device__ __forceinline__ float fast_rsqrt(float x) {
    float r;
    asm("rsqrt.approx.f32 %0, %1;" : "=f"(r) : "f"(x));
    return r;
}

__device__ __forceinline__ void mecanum_row(
    float theta, float vx, float vy, float wz,
    float u0, float u1, float u2,
    float& ax, float& ay, float& aw)
{
    float st, ct;
    fast_sincos(theta, st, ct);

    // local velocity (rotation by -theta)
    float lvx =  ct * vx + st * vy;
    float lvy = -st * vx + ct * vy;

    // wheel velocities (needed only for the softsign friction terms)
    float p  = mk::INV_R * (lvx + lvy);
    float m  = mk::INV_R * (lvx - lvy);
    float lz = mk::L_R * wz;
    float w0 = m - lz;
    float w1 = p + lz;
    float w2 = p - lz;
    float w3 = m + lz;

    float ss0 = w0 * fast_rsqrt(w0 * w0 + mk::EPS);
    float ss1 = w1 * fast_rsqrt(w1 * w1 + mk::EPS);
    float ss2 = w2 * fast_rsqrt(w2 * w2 + mk::EPS);
    float ss3 = w3 * fast_rsqrt(w3 * w3 + mk::EPS);

    // sign-pattern sums:  S0 = ++++ , S1 = -++- , S2 = -+-+
    float a = ss0 + ss3, b = ss1 + ss2;
    float S0 = a + b;
    float S1 = b - a;
    float S2 = (ss1 - ss2) + (ss3 - ss0);

    // collapsed local acceleration
    float la0 = mk::A_XY * u0 - mk::B_XY * lvx - mk::C_XY * S0;
    float la1 = mk::A_XY * u1 - mk::B_XY * lvy - mk::C_XY * S1;
    float la2 = mk::A_W  * u2 - mk::B_W  * wz  - mk::C_W  * S2;

    // rotate back by +theta (A^T)
    ax = ct * la0 - st * la1;
    ay = st * la0 + ct * la1;
    aw = la2;
}

// ---- One row per thread: R7 winner shape + collapsed math + __ldg loads ----
// Per row: 2x float2 state loads via the nc/texture path (8-aligned; the
// unused x,y fields are never loaded), 3 scalar ctrl loads (nc), 3x float2
// __stcs streaming stores (write-only output -> evict-first keeps the 72MB
// of inputs L2-resident across graph replays).
__global__ void __launch_bounds__(256, 8)
mecanum_row_kernel(const float* __restrict__ state,
                   const float* __restrict__ ctrl,
                   float* __restrict__ out,
                   int B)
{
    int i = blockIdx.x * blockDim.x + threadIdx.x;
    if (i >= B) return;

    const float2* s2 = reinterpret_cast<const float2*>(state + 6 * (size_t)i + 2);
    float2 tv = __ldg(s2 + 0);        // theta, vx
    float2 vw = __ldg(s2 + 1);        // vy, wz

    const float* u = ctrl + 3 * (size_t)i;
    float u0 = __ldg(u + 0), u1 = __ldg(u + 1), u2 = __ldg(u + 2);

    float ax, ay, aw;
    mecanum_row(tv.x, tv.y, vw.x, vw.y, u0, u1, u2, ax, ay, aw);

    float2* o2 = reinterpret_cast<float2*>(out + 6 * (size_t)i);
    __stcs(o2 + 0, make_float2(tv.y, vw.x));   // vx, vy
    __stcs(o2 + 1, make_float2(vw.y, ax));     // wz, ax
    __stcs(o2 + 2, make_float2(ay, aw));       // ay, aw
}

extern "C" void kernel_launch(void* const* d_in, const int* in_sizes, int n_in,
                              void* d_out, int out_size)
{
    // metadata order: t (1), state (B*6), control_duty (B*3)
    const float* state = (const float*)d_in[1];
    const float* ctrl  = (const float*)d_in[2];
    float* out = (float*)d_out;
    int B = in_sizes[1] / 6;

    int threads = 256;
    int blocks = (B + threads - 1) / threads;
    mecanum_row_kernel<<<blocks, threads>>>(state, ctrl, out, B);
}